// round 10
// baseline (speedup 1.0000x reference)
#include <cuda_runtime.h>
#include <cuda_bf16.h>
#include <cuda_fp16.h>
#include <cstdint>
#include <math.h>

#define NROWS 8192
#define HID   128
#define OUTC  64
#define GDIM  192          // [h(64) | x(128)]
#define TK    384          // [hi(192) | lo(192)] fp16
#define EMAX  262144
#define RET_ELEMS (NROWS * NROWS)

// ---------------------------------------------------------------------------
// Scratch (device globals)
// ---------------------------------------------------------------------------
__device__ float g_y1[NROWS * HID];
__device__ float g_z1[NROWS * HID];
__device__ float g_h1[NROWS * OUTC];
__device__ float g_y2[NROWS * OUTC];
__device__ float g_z2[NROWS * OUTC];
__device__ float g_h [NROWS * OUTC];          // fp32 h for BN
__device__ __half g_Gb[NROWS * TK];           // [Gh | Gl] fp16 hi/lo split
__device__ float g_stats[2 * OUTC];
// CSR scratch
__device__ int g_deg[NROWS];
__device__ int g_off[NROWS + 1];
__device__ int g_cur[NROWS];
__device__ int g_csr[EMAX];

// ---------------------------------------------------------------------------
// helpers
// ---------------------------------------------------------------------------
__device__ __forceinline__ uint32_t smem_u32(const void* p) {
    uint32_t a;
    asm("{ .reg .u64 t; cvta.to.shared.u64 t, %1; cvt.u32.u64 %0, t; }" : "=r"(a) : "l"(p));
    return a;
}
__device__ __forceinline__ void ldm_x4(uint32_t* r, uint32_t addr) {
    asm volatile("ldmatrix.sync.aligned.m8n8.x4.shared.b16 {%0,%1,%2,%3}, [%4];"
                 : "=r"(r[0]), "=r"(r[1]), "=r"(r[2]), "=r"(r[3]) : "r"(addr));
}
__device__ __forceinline__ void mma16816(float* d, const uint32_t* a, const uint32_t* b) {
    asm volatile("mma.sync.aligned.m16n8k16.row.col.f32.f16.f16.f32 "
                 "{%0,%1,%2,%3}, {%4,%5,%6,%7}, {%8,%9}, {%0,%1,%2,%3};"
                 : "+f"(d[0]), "+f"(d[1]), "+f"(d[2]), "+f"(d[3])
                 : "r"(a[0]), "r"(a[1]), "r"(a[2]), "r"(a[3]), "r"(b[0]), "r"(b[1]));
}
__device__ __forceinline__ void cp16(uint32_t smem_dst, const void* gsrc) {
    asm volatile("cp.async.cg.shared.global [%0], [%1], 16;"
                 :: "r"(smem_dst), "l"(gsrc) : "memory");
}
__device__ __forceinline__ void cp_commit() {
    asm volatile("cp.async.commit_group;" ::: "memory");
}
template <int N>
__device__ __forceinline__ void cp_wait() {
    asm volatile("cp.async.wait_group %0;" :: "n"(N) : "memory");
}

// ---------------------------------------------------------------------------
// CSR build: zero -> histogram -> scan -> scatter (int4 edge loads)
// ---------------------------------------------------------------------------
__global__ void zero_small() {
    int i = blockIdx.x * blockDim.x + threadIdx.x;
    if (i < NROWS) g_deg[i] = 0;
    if (i < 2 * OUTC) g_stats[i] = 0.f;
}

__global__ void hist_kernel(const int* __restrict__ dst, int E) {
    int i = blockIdx.x * blockDim.x + threadIdx.x;
    int stride = gridDim.x * blockDim.x;
    int n4 = E >> 2;
    const int4* d4 = (const int4*)dst;
    for (int e = i; e < n4; e += stride) {
        int4 d = d4[e];
        atomicAdd(&g_deg[d.x], 1);
        atomicAdd(&g_deg[d.y], 1);
        atomicAdd(&g_deg[d.z], 1);
        atomicAdd(&g_deg[d.w], 1);
    }
}

__global__ void __launch_bounds__(1024) scan_kernel() {
    __shared__ int ssum[1024];
    int t = threadIdx.x;
    int v[8];
    int tot = 0;
#pragma unroll
    for (int j = 0; j < 8; j++) { v[j] = g_deg[t * 8 + j]; tot += v[j]; }
    ssum[t] = tot;
    __syncthreads();
    for (int d = 1; d < 1024; d <<= 1) {
        int x = (t >= d) ? ssum[t - d] : 0;
        __syncthreads();
        ssum[t] += x;
        __syncthreads();
    }
    int run = ssum[t] - tot;   // exclusive prefix
#pragma unroll
    for (int j = 0; j < 8; j++) {
        g_off[t * 8 + j] = run;
        g_cur[t * 8 + j] = run;
        run += v[j];
    }
    if (t == 1023) g_off[NROWS] = run;
}

__global__ void scatter_kernel(const int* __restrict__ src,
                               const int* __restrict__ dst, int E) {
    int i = blockIdx.x * blockDim.x + threadIdx.x;
    int stride = gridDim.x * blockDim.x;
    int n4 = E >> 2;
    const int4* s4 = (const int4*)src;
    const int4* d4 = (const int4*)dst;
    for (int e = i; e < n4; e += stride) {
        int4 s = s4[e];
        int4 d = d4[e];
        int p0 = atomicAdd(&g_cur[d.x], 1); g_csr[p0] = s.x;
        int p1 = atomicAdd(&g_cur[d.y], 1); g_csr[p1] = s.y;
        int p2 = atomicAdd(&g_cur[d.z], 1); g_csr[p2] = s.z;
        int p3 = atomicAdd(&g_cur[d.w], 1); g_csr[p3] = s.w;
    }
}

// ---------------------------------------------------------------------------
// CSR gather segment-sum
// ---------------------------------------------------------------------------
template <int TPD>
__global__ void __launch_bounds__(256) gather_kernel(
    const float* __restrict__ feat, float* __restrict__ out)
{
    const int F = TPD * 4;
    int g = (blockIdx.x * blockDim.x + threadIdx.x) / TPD;
    int lane = threadIdx.x % TPD;
    if (g >= NROWS) return;
    int b = g_off[g];
    int e = g_off[g + 1];
    float4 acc = make_float4(0.f, 0.f, 0.f, 0.f);
    float4 acc2 = make_float4(0.f, 0.f, 0.f, 0.f);
    int i = b;
    for (; i + 1 < e; i += 2) {
        int s0 = g_csr[i];
        int s1 = g_csr[i + 1];
        float4 v0 = *(const float4*)(feat + (size_t)s0 * F + lane * 4);
        float4 v1 = *(const float4*)(feat + (size_t)s1 * F + lane * 4);
        acc.x += v0.x; acc.y += v0.y; acc.z += v0.z; acc.w += v0.w;
        acc2.x += v1.x; acc2.y += v1.y; acc2.z += v1.z; acc2.w += v1.w;
    }
    if (i < e) {
        int s0 = g_csr[i];
        float4 v0 = *(const float4*)(feat + (size_t)s0 * F + lane * 4);
        acc.x += v0.x; acc.y += v0.y; acc.z += v0.z; acc.w += v0.w;
    }
    acc.x += acc2.x; acc.y += acc2.y; acc.z += acc2.z; acc.w += acc2.w;
    *(float4*)(out + (size_t)g * F + lane * 4) = acc;
}

// ---------------------------------------------------------------------------
// Small GEMM (unchanged, known-good)
// ---------------------------------------------------------------------------
__global__ void __launch_bounds__(256) small_gemm(
    const float* __restrict__ A, const float* __restrict__ abias,
    const float* __restrict__ B, const float* __restrict__ cbias,
    float* __restrict__ C, int M, int Nc, int relu)
{
    __shared__ float As[16][64];
    __shared__ float Bs[16][64];
    const int row0 = blockIdx.x * 64;
    const int col0 = blockIdx.y * 64;
    const int tid = threadIdx.x;
    const int tx = tid & 15, ty = tid >> 4;

    float acc[4][4];
#pragma unroll
    for (int i = 0; i < 4; i++)
#pragma unroll
        for (int j = 0; j < 4; j++) acc[i][j] = 0.f;

    for (int k0 = 0; k0 < HID; k0 += 16) {
        {
            int r = tid >> 2;
            int c4 = (tid & 3) * 4;
            float4 v = *(const float4*)(A + (size_t)(row0 + r) * HID + k0 + c4);
            if (relu) {
                v.x = fmaxf(v.x + abias[k0 + c4 + 0], 0.f);
                v.y = fmaxf(v.y + abias[k0 + c4 + 1], 0.f);
                v.z = fmaxf(v.z + abias[k0 + c4 + 2], 0.f);
                v.w = fmaxf(v.w + abias[k0 + c4 + 3], 0.f);
            }
            As[c4 + 0][r] = v.x; As[c4 + 1][r] = v.y;
            As[c4 + 2][r] = v.z; As[c4 + 3][r] = v.w;
        }
        {
            int kr = tid >> 4;
            int c = (tid & 15) * 4;
            float4 v = *(const float4*)(B + (size_t)(k0 + kr) * Nc + col0 + c);
            *(float4*)&Bs[kr][c] = v;
        }
        __syncthreads();
#pragma unroll
        for (int kk = 0; kk < 16; kk++) {
            float av[4], bv[4];
#pragma unroll
            for (int i = 0; i < 4; i++) av[i] = As[kk][ty * 4 + i];
#pragma unroll
            for (int j = 0; j < 4; j++) bv[j] = Bs[kk][tx * 4 + j];
#pragma unroll
            for (int i = 0; i < 4; i++)
#pragma unroll
                for (int j = 0; j < 4; j++) acc[i][j] += av[i] * bv[j];
        }
        __syncthreads();
    }
#pragma unroll
    for (int i = 0; i < 4; i++)
#pragma unroll
        for (int j = 0; j < 4; j++) {
            int c = col0 + tx * 4 + j;
            float cb = cbias ? cbias[c] : 0.f;
            C[(size_t)(row0 + ty * 4 + i) * Nc + c] = acc[i][j] + cb;
        }
}

// ---------------------------------------------------------------------------
// Build h, fp16 hi/lo split of G=[h|x] into g_Gb, BN stats.
// ---------------------------------------------------------------------------
__device__ __forceinline__ void split_store(__half* Gb, size_t r, int col, float v) {
    __half hi = __float2half(v);
    __half lo = __float2half(v - __half2float(hi));
    Gb[r * TK + col]        = hi;
    Gb[r * TK + GDIM + col] = lo;
}

__global__ void build_h(const float* __restrict__ h1, const float* __restrict__ z2,
                        const float* __restrict__ w2b, const float* __restrict__ x,
                        const float* __restrict__ epsv,
                        float* __restrict__ h_out, __half* __restrict__ Gb,
                        float* __restrict__ stats)
{
    __shared__ float ssum[OUTC];
    __shared__ float ssq[OUTC];
    int c = threadIdx.x;
    int ty = threadIdx.y;
    if (ty == 0) { ssum[c] = 0.f; ssq[c] = 0.f; }
    __syncthreads();

    size_t r = blockIdx.x * 8 + ty;
    float e  = epsv[r];
    float hv = (1.f - e) * h1[r * OUTC + c] + e * (z2[r * OUTC + c] + w2b[c]);
    h_out[r * OUTC + c] = hv;
    split_store(Gb, r, c, hv);
    split_store(Gb, r, OUTC + c,      x[r * HID + c]);
    split_store(Gb, r, OUTC + 64 + c, x[r * HID + 64 + c]);
    atomicAdd(&ssum[c], hv);
    atomicAdd(&ssq[c], hv * hv);
    __syncthreads();
    if (ty == 0) {
        atomicAdd(&stats[c], ssum[c]);
        atomicAdd(&stats[OUTC + c], ssq[c]);
    }
}

__global__ void bn_out(const float* __restrict__ h, const float* __restrict__ stats,
                       const float* __restrict__ gamma, const float* __restrict__ beta,
                       float* __restrict__ out)
{
    int i = blockIdx.x * blockDim.x + threadIdx.x;
    if (i >= NROWS * OUTC) return;
    int c = i & 63;
    float inv = 1.f / (float)NROWS;
    float mean = stats[c] * inv;
    float var  = stats[OUTC + c] * inv - mean * mean;
    out[i] = (h[i] - mean) * rsqrtf(var + 1e-5f) * gamma[c] + beta[c];
}

// ---------------------------------------------------------------------------
// HMMA SYRK over fp16 [Hh|Hl] concat (K=384, 24 k16-steps).
// Both A and B double-buffered in K=96 chunks (chunk c pairs A[c] with B[c]
// at the same k-range). Prologue only waits on one 53KB chunk pair instead
// of the full 125KB B+A0 -> ~4x less exposed load latency per tile.
// ---------------------------------------------------------------------------
#define CH_STRIDE 208                           // 96 fp16 padded to 104 (208B)
#define CH_BYTES  (128 * CH_STRIDE)             // 26624
#define SYRK_SMEM (4 * CH_BYTES)                // 106496 (A0,A1,B0,B1)

__device__ __forceinline__ void load_chunk(uint32_t dstBase,
                                           const __half* __restrict__ Gsrc,
                                           int chunk, int tid) {
#pragma unroll 2
    for (int i = tid; i < 128 * 12; i += 256) {
        int row = i / 12, q = i % 12;
        cp16(dstBase + row * CH_STRIDE + q * 16,
             Gsrc + (size_t)row * TK + chunk * 96 + q * 8);
    }
}

__global__ void __launch_bounds__(256, 1) big_syrk_mma(
    const __half* __restrict__ Gb, float* __restrict__ C)
{
    extern __shared__ char smem[];
    const uint32_t smA0 = smem_u32(smem);
    const uint32_t smA1 = smA0 + CH_BYTES;
    const uint32_t smB0 = smA1 + CH_BYTES;
    const uint32_t smB1 = smB0 + CH_BYTES;

    const int tid = threadIdx.x;
    const int wid = tid >> 5;
    const int lid = tid & 31;

    int idx = blockIdx.x;
    int bi = 0;
    while (bi < 63 && (64 * (bi + 1) - ((bi + 1) * bi) / 2) <= idx) bi++;
    int bj = bi + (idx - (64 * bi - (bi * (bi - 1)) / 2));

    const __half* GbA = Gb + (size_t)(bi * 128) * TK;
    const __half* GbB = Gb + (size_t)(bj * 128) * TK;

    // prologue: chunk0 (A0,B0) -> group1; chunk1 (A1,B1) -> group2
    load_chunk(smA0, GbA, 0, tid);
    load_chunk(smB0, GbB, 0, tid);
    cp_commit();
    load_chunk(smA1, GbA, 1, tid);
    load_chunk(smB1, GbB, 1, tid);
    cp_commit();

    const int wm = wid >> 2;
    const int wn = wid & 3;
    const int m_base = wm * 64;
    const int n0 = wn * 32;

    const int aRow = m_base + (lid & 15);
    const int aColH = (lid >> 4) * 8;
    const int bRow = n0 + ((lid >> 4) * 8) + (lid & 7);
    const int bColH = ((lid >> 3) & 1) * 8;

    float acc[4][4][4];
#pragma unroll
    for (int mf = 0; mf < 4; mf++)
#pragma unroll
        for (int nf = 0; nf < 4; nf++)
#pragma unroll
            for (int q = 0; q < 4; q++) acc[mf][nf][q] = 0.f;

#pragma unroll
    for (int c = 0; c < 4; c++) {
        if (c < 3) cp_wait<1>(); else cp_wait<0>();
        __syncthreads();
        const uint32_t smAc = (c & 1) ? smA1 : smA0;
        const uint32_t smBc = (c & 1) ? smB1 : smB0;

#pragma unroll
        for (int s = 0; s < 6; s++) {
            const int kk = s * 16;                // same k-range for A and B
            uint32_t a[4][4];
#pragma unroll
            for (int mf = 0; mf < 4; mf++)
                ldm_x4(a[mf], smAc + (uint32_t)((aRow + mf * 16) * CH_STRIDE
                                                + (kk + aColH) * 2));
            uint32_t b[4][2];
#pragma unroll
            for (int q = 0; q < 2; q++) {
                uint32_t r[4];
                ldm_x4(r, smBc + (uint32_t)((bRow + q * 16) * CH_STRIDE
                                            + (kk + bColH) * 2));
                b[2 * q + 0][0] = r[0]; b[2 * q + 0][1] = r[1];
                b[2 * q + 1][0] = r[2]; b[2 * q + 1][1] = r[3];
            }
#pragma unroll
            for (int mf = 0; mf < 4; mf++)
#pragma unroll
                for (int nf = 0; nf < 4; nf++)
                    mma16816(acc[mf][nf], a[mf], b[nf]);
        }
        __syncthreads();
        if (c + 2 < 4) {
            load_chunk((c & 1) ? smA1 : smA0, GbA, c + 2, tid);
            load_chunk((c & 1) ? smB1 : smB0, GbB, c + 2, tid);
            cp_commit();
        }
    }

    // ---- epilogue ----
    const int r0g = bi * 128, c0g = bj * 128;
    const int lrow = lid >> 2;
    const int lcol = (lid & 3) * 2;

#pragma unroll
    for (int mf = 0; mf < 4; mf++) {
#pragma unroll
        for (int nf = 0; nf < 4; nf++) {
            int row = m_base + mf * 16 + lrow;
            int col = n0 + nf * 8 + lcol;
            float2 v0 = make_float2(0.5f * acc[mf][nf][0], 0.5f * acc[mf][nf][1]);
            float2 v1 = make_float2(0.5f * acc[mf][nf][2], 0.5f * acc[mf][nf][3]);
            *(float2*)(C + (size_t)(r0g + row) * NROWS + c0g + col)     = v0;
            *(float2*)(C + (size_t)(r0g + row + 8) * NROWS + c0g + col) = v1;
        }
    }

    if (bi != bj) {
        __syncthreads();                       // smem tiles no longer needed
        float* smT = (float*)smem;             // [128 cols][132] transpose buf
#pragma unroll
        for (int mf = 0; mf < 4; mf++) {
#pragma unroll
            for (int nf = 0; nf < 4; nf++) {
                int row = m_base + mf * 16 + lrow;
                int col = n0 + nf * 8 + lcol;
                smT[(col + 0) * 132 + row]     = 0.5f * acc[mf][nf][0];
                smT[(col + 1) * 132 + row]     = 0.5f * acc[mf][nf][1];
                smT[(col + 0) * 132 + row + 8] = 0.5f * acc[mf][nf][2];
                smT[(col + 1) * 132 + row + 8] = 0.5f * acc[mf][nf][3];
            }
        }
        __syncthreads();
        for (int i = tid; i < 128 * 32; i += 256) {
            int c = i >> 5, q = i & 31;
            float4 v = *(float4*)&smT[c * 132 + q * 4];
            *(float4*)(C + (size_t)(c0g + c) * NROWS + r0g + q * 4) = v;
        }
    }
}

// ---------------------------------------------------------------------------
// Launch
// Inputs: 0:x 1:adj 2:src 3:dst 4:fc_w 5:fc_b 6:w1 7:w1_b 8:w2 9:w2_b
//         10:epsilon 11:gamma 12:beta
// Launch order puts small_gemm(y1) at slot 3 so the fixed ncu capture window
// (which has been sampling the 4th launch every round) profiles it.
// ---------------------------------------------------------------------------
extern "C" void kernel_launch(void* const* d_in, const int* in_sizes, int n_in,
                              void* d_out, int out_size)
{
    const float* x     = (const float*)d_in[0];
    const int*   src   = (const int*)d_in[2];
    const int*   dst   = (const int*)d_in[3];
    const float* fc_w  = (const float*)d_in[4];
    const float* fc_b  = (const float*)d_in[5];
    const float* w1    = (const float*)d_in[6];
    const float* w1_b  = (const float*)d_in[7];
    const float* w2    = (const float*)d_in[8];
    const float* w2_b  = (const float*)d_in[9];
    const float* epsv  = (const float*)d_in[10];
    const float* gamma = (const float*)d_in[11];
    const float* beta  = (const float*)d_in[12];
    const int E = in_sizes[2];

    float* out_ret = (float*)d_out;
    float* out_bn  = (float*)d_out + (size_t)RET_ELEMS;

    float *y1, *z1, *h1, *y2, *z2, *h, *stats;
    __half* Gb;
    cudaGetSymbolAddress((void**)&y1, g_y1);
    cudaGetSymbolAddress((void**)&z1, g_z1);
    cudaGetSymbolAddress((void**)&h1, g_h1);
    cudaGetSymbolAddress((void**)&y2, g_y2);
    cudaGetSymbolAddress((void**)&z2, g_z2);
    cudaGetSymbolAddress((void**)&h,  g_h);
    cudaGetSymbolAddress((void**)&Gb, g_Gb);
    cudaGetSymbolAddress((void**)&stats, g_stats);

    cudaFuncSetAttribute(big_syrk_mma, cudaFuncAttributeMaxDynamicSharedMemorySize,
                         SYRK_SMEM);

    // CSR build front half
    zero_small<<<(NROWS + 255) / 256, 256>>>();            // 0
    hist_kernel<<<256, 256>>>(dst, E);                     // 1
    scan_kernel<<<1, 1024>>>();                            // 2

    // y1 = x @ w1 (slot 3 -> profiled) ; h1 = x @ fc_w + fc_b
    small_gemm<<<dim3(NROWS / 64, HID / 64), 256>>>(x, nullptr, w1, nullptr,
                                                    y1, NROWS, HID, 0);   // 3
    small_gemm<<<dim3(NROWS / 64, OUTC / 64), 256>>>(x, nullptr, fc_w, fc_b,
                                                     h1, NROWS, OUTC, 0); // 4

    // CSR scatter (only needs scan), then gathers
    scatter_kernel<<<256, 256>>>(src, dst, E);             // 5

    // z1 = segsum(y1)
    gather_kernel<32><<<NROWS * 32 / 256, 256>>>(y1, z1);  // 6

    // y2 = relu(z1 + w1_b) @ w2
    small_gemm<<<dim3(NROWS / 64, OUTC / 64), 256>>>(z1, w1_b, w2, nullptr,
                                                     y2, NROWS, OUTC, 1); // 7
    // z2 = segsum(y2)
    gather_kernel<16><<<NROWS * 16 / 256, 256>>>(y2, z2);  // 8

    build_h<<<NROWS / 8, dim3(64, 8)>>>(h1, z2, w2_b, x, epsv, h, Gb, stats); // 9
    bn_out<<<(NROWS * OUTC + 255) / 256, 256>>>(h, stats, gamma, beta, out_bn); // 10

    big_syrk_mma<<<(64 * 65) / 2, 256, SYRK_SMEM>>>(Gb, out_ret); // 11
}

// round 13
// speedup vs baseline: 1.3194x; 1.3194x over previous
// R12 resubmission (3rd attempt) — byte-equivalent to R11; container failures
// at R0 (stub) and R6 (later-passing source) establish this failure mode as
// infra-side, not source-side.
#include <cuda_runtime.h>
#include <cuda_bf16.h>
#include <cuda_fp16.h>
#include <cstdint>
#include <math.h>

#define NROWS 8192
#define HID   128
#define OUTC  64
#define GDIM  192          // [h(64) | x(128)]
#define TK    192          // fp16 G (hi only; cross-term analysis shows the
                           // lo-half contributed only lo*lo ~ 2^-24 -> dropped)
#define EMAX  262144
#define RET_ELEMS (NROWS * NROWS)

// ---------------------------------------------------------------------------
// Scratch (device globals)
// ---------------------------------------------------------------------------
__device__ float g_y1[NROWS * HID];
__device__ float g_z1[NROWS * HID];
__device__ float g_h1[NROWS * OUTC];
__device__ float g_y2[NROWS * OUTC];
__device__ float g_z2[NROWS * OUTC];
__device__ float g_h [NROWS * OUTC];          // fp32 h for BN
__device__ __half g_Gb[NROWS * TK];           // fp16 G = [h | x]
__device__ float g_stats[2 * OUTC];
// CSR scratch
__device__ int g_deg[NROWS];
__device__ int g_off[NROWS + 1];
__device__ int g_cur[NROWS];
__device__ int g_csr[EMAX];

// ---------------------------------------------------------------------------
// helpers
// ---------------------------------------------------------------------------
__device__ __forceinline__ uint32_t smem_u32(const void* p) {
    uint32_t a;
    asm("{ .reg .u64 t; cvta.to.shared.u64 t, %1; cvt.u32.u64 %0, t; }" : "=r"(a) : "l"(p));
    return a;
}
__device__ __forceinline__ void ldm_x4(uint32_t* r, uint32_t addr) {
    asm volatile("ldmatrix.sync.aligned.m8n8.x4.shared.b16 {%0,%1,%2,%3}, [%4];"
                 : "=r"(r[0]), "=r"(r[1]), "=r"(r[2]), "=r"(r[3]) : "r"(addr));
}
__device__ __forceinline__ void mma16816(float* d, const uint32_t* a, const uint32_t* b) {
    asm volatile("mma.sync.aligned.m16n8k16.row.col.f32.f16.f16.f32 "
                 "{%0,%1,%2,%3}, {%4,%5,%6,%7}, {%8,%9}, {%0,%1,%2,%3};"
                 : "+f"(d[0]), "+f"(d[1]), "+f"(d[2]), "+f"(d[3])
                 : "r"(a[0]), "r"(a[1]), "r"(a[2]), "r"(a[3]), "r"(b[0]), "r"(b[1]));
}
__device__ __forceinline__ void cp16(uint32_t smem_dst, const void* gsrc) {
    asm volatile("cp.async.cg.shared.global [%0], [%1], 16;"
                 :: "r"(smem_dst), "l"(gsrc) : "memory");
}
__device__ __forceinline__ void cp_commit() {
    asm volatile("cp.async.commit_group;" ::: "memory");
}
template <int N>
__device__ __forceinline__ void cp_wait() {
    asm volatile("cp.async.wait_group %0;" :: "n"(N) : "memory");
}

// ---------------------------------------------------------------------------
// CSR build: zero -> histogram -> scan -> scatter (int4 edge loads)
// ---------------------------------------------------------------------------
__global__ void zero_small() {
    int i = blockIdx.x * blockDim.x + threadIdx.x;
    if (i < NROWS) g_deg[i] = 0;
    if (i < 2 * OUTC) g_stats[i] = 0.f;
}

__global__ void hist_kernel(const int* __restrict__ dst, int E) {
    int i = blockIdx.x * blockDim.x + threadIdx.x;
    int stride = gridDim.x * blockDim.x;
    int n4 = E >> 2;
    const int4* d4 = (const int4*)dst;
    for (int e = i; e < n4; e += stride) {
        int4 d = d4[e];
        atomicAdd(&g_deg[d.x], 1);
        atomicAdd(&g_deg[d.y], 1);
        atomicAdd(&g_deg[d.z], 1);
        atomicAdd(&g_deg[d.w], 1);
    }
}

__global__ void __launch_bounds__(1024) scan_kernel() {
    __shared__ int ssum[1024];
    int t = threadIdx.x;
    int v[8];
    int tot = 0;
#pragma unroll
    for (int j = 0; j < 8; j++) { v[j] = g_deg[t * 8 + j]; tot += v[j]; }
    ssum[t] = tot;
    __syncthreads();
    for (int d = 1; d < 1024; d <<= 1) {
        int x = (t >= d) ? ssum[t - d] : 0;
        __syncthreads();
        ssum[t] += x;
        __syncthreads();
    }
    int run = ssum[t] - tot;   // exclusive prefix
#pragma unroll
    for (int j = 0; j < 8; j++) {
        g_off[t * 8 + j] = run;
        g_cur[t * 8 + j] = run;
        run += v[j];
    }
    if (t == 1023) g_off[NROWS] = run;
}

__global__ void scatter_kernel(const int* __restrict__ src,
                               const int* __restrict__ dst, int E) {
    int i = blockIdx.x * blockDim.x + threadIdx.x;
    int stride = gridDim.x * blockDim.x;
    int n4 = E >> 2;
    const int4* s4 = (const int4*)src;
    const int4* d4 = (const int4*)dst;
    for (int e = i; e < n4; e += stride) {
        int4 s = s4[e];
        int4 d = d4[e];
        int p0 = atomicAdd(&g_cur[d.x], 1); g_csr[p0] = s.x;
        int p1 = atomicAdd(&g_cur[d.y], 1); g_csr[p1] = s.y;
        int p2 = atomicAdd(&g_cur[d.z], 1); g_csr[p2] = s.z;
        int p3 = atomicAdd(&g_cur[d.w], 1); g_csr[p3] = s.w;
    }
}

// ---------------------------------------------------------------------------
// CSR gather segment-sum
// ---------------------------------------------------------------------------
template <int TPD>
__global__ void __launch_bounds__(256) gather_kernel(
    const float* __restrict__ feat, float* __restrict__ out)
{
    const int F = TPD * 4;
    int g = (blockIdx.x * blockDim.x + threadIdx.x) / TPD;
    int lane = threadIdx.x % TPD;
    if (g >= NROWS) return;
    int b = g_off[g];
    int e = g_off[g + 1];
    float4 acc = make_float4(0.f, 0.f, 0.f, 0.f);
    float4 acc2 = make_float4(0.f, 0.f, 0.f, 0.f);
    int i = b;
    for (; i + 1 < e; i += 2) {
        int s0 = g_csr[i];
        int s1 = g_csr[i + 1];
        float4 v0 = *(const float4*)(feat + (size_t)s0 * F + lane * 4);
        float4 v1 = *(const float4*)(feat + (size_t)s1 * F + lane * 4);
        acc.x += v0.x; acc.y += v0.y; acc.z += v0.z; acc.w += v0.w;
        acc2.x += v1.x; acc2.y += v1.y; acc2.z += v1.z; acc2.w += v1.w;
    }
    if (i < e) {
        int s0 = g_csr[i];
        float4 v0 = *(const float4*)(feat + (size_t)s0 * F + lane * 4);
        acc.x += v0.x; acc.y += v0.y; acc.z += v0.z; acc.w += v0.w;
    }
    acc.x += acc2.x; acc.y += acc2.y; acc.z += acc2.z; acc.w += acc2.w;
    *(float4*)(out + (size_t)g * F + lane * 4) = acc;
}

// ---------------------------------------------------------------------------
// Small GEMM (unchanged, known-good)
// ---------------------------------------------------------------------------
__global__ void __launch_bounds__(256) small_gemm(
    const float* __restrict__ A, const float* __restrict__ abias,
    const float* __restrict__ B, const float* __restrict__ cbias,
    float* __restrict__ C, int M, int Nc, int relu)
{
    __shared__ float As[16][64];
    __shared__ float Bs[16][64];
    const int row0 = blockIdx.x * 64;
    const int col0 = blockIdx.y * 64;
    const int tid = threadIdx.x;
    const int tx = tid & 15, ty = tid >> 4;

    float acc[4][4];
#pragma unroll
    for (int i = 0; i < 4; i++)
#pragma unroll
        for (int j = 0; j < 4; j++) acc[i][j] = 0.f;

    for (int k0 = 0; k0 < HID; k0 += 16) {
        {
            int r = tid >> 2;
            int c4 = (tid & 3) * 4;
            float4 v = *(const float4*)(A + (size_t)(row0 + r) * HID + k0 + c4);
            if (relu) {
                v.x = fmaxf(v.x + abias[k0 + c4 + 0], 0.f);
                v.y = fmaxf(v.y + abias[k0 + c4 + 1], 0.f);
                v.z = fmaxf(v.z + abias[k0 + c4 + 2], 0.f);
                v.w = fmaxf(v.w + abias[k0 + c4 + 3], 0.f);
            }
            As[c4 + 0][r] = v.x; As[c4 + 1][r] = v.y;
            As[c4 + 2][r] = v.z; As[c4 + 3][r] = v.w;
        }
        {
            int kr = tid >> 4;
            int c = (tid & 15) * 4;
            float4 v = *(const float4*)(B + (size_t)(k0 + kr) * Nc + col0 + c);
            *(float4*)&Bs[kr][c] = v;
        }
        __syncthreads();
#pragma unroll
        for (int kk = 0; kk < 16; kk++) {
            float av[4], bv[4];
#pragma unroll
            for (int i = 0; i < 4; i++) av[i] = As[kk][ty * 4 + i];
#pragma unroll
            for (int j = 0; j < 4; j++) bv[j] = Bs[kk][tx * 4 + j];
#pragma unroll
            for (int i = 0; i < 4; i++)
#pragma unroll
                for (int j = 0; j < 4; j++) acc[i][j] += av[i] * bv[j];
        }
        __syncthreads();
    }
#pragma unroll
    for (int i = 0; i < 4; i++)
#pragma unroll
        for (int j = 0; j < 4; j++) {
            int c = col0 + tx * 4 + j;
            float cb = cbias ? cbias[c] : 0.f;
            C[(size_t)(row0 + ty * 4 + i) * Nc + c] = acc[i][j] + cb;
        }
}

// ---------------------------------------------------------------------------
// Build h, fp16 G=[h|x] into g_Gb, BN stats.
// ---------------------------------------------------------------------------
__global__ void build_h(const float* __restrict__ h1, const float* __restrict__ z2,
                        const float* __restrict__ w2b, const float* __restrict__ x,
                        const float* __restrict__ epsv,
                        float* __restrict__ h_out, __half* __restrict__ Gb,
                        float* __restrict__ stats)
{
    __shared__ float ssum[OUTC];
    __shared__ float ssq[OUTC];
    int c = threadIdx.x;
    int ty = threadIdx.y;
    if (ty == 0) { ssum[c] = 0.f; ssq[c] = 0.f; }
    __syncthreads();

    size_t r = blockIdx.x * 8 + ty;
    float e  = epsv[r];
    float hv = (1.f - e) * h1[r * OUTC + c] + e * (z2[r * OUTC + c] + w2b[c]);
    h_out[r * OUTC + c] = hv;
    Gb[r * TK + c]             = __float2half(hv);
    Gb[r * TK + OUTC + c]      = __float2half(x[r * HID + c]);
    Gb[r * TK + OUTC + 64 + c] = __float2half(x[r * HID + 64 + c]);
    atomicAdd(&ssum[c], hv);
    atomicAdd(&ssq[c], hv * hv);
    __syncthreads();
    if (ty == 0) {
        atomicAdd(&stats[c], ssum[c]);
        atomicAdd(&stats[OUTC + c], ssq[c]);
    }
}

__global__ void bn_out(const float* __restrict__ h, const float* __restrict__ stats,
                       const float* __restrict__ gamma, const float* __restrict__ beta,
                       float* __restrict__ out)
{
    int i = blockIdx.x * blockDim.x + threadIdx.x;
    if (i >= NROWS * OUTC) return;
    int c = i & 63;
    float inv = 1.f / (float)NROWS;
    float mean = stats[c] * inv;
    float var  = stats[OUTC + c] * inv - mean * mean;
    out[i] = (h[i] - mean) * rsqrtf(var + 1e-5f) * gamma[c] + beta[c];
}

// ---------------------------------------------------------------------------
// HMMA SYRK over plain fp16 G (K=192, 12 k16-steps — half the MMA work of
// the split version at the same error level: the dropped lo*lo term is
// ~2^-24 relative, while the dominating cross terms were missing either way).
// 2 chunks of K=96, both prefetched in the prologue; no mid-loop loads.
// ---------------------------------------------------------------------------
#define CH_STRIDE 208                           // 96 fp16 padded to 104 (208B)
#define CH_BYTES  (128 * CH_STRIDE)             // 26624
#define SYRK_SMEM (4 * CH_BYTES)                // 106496 (A0,A1,B0,B1)

__device__ __forceinline__ void load_chunk(uint32_t dstBase,
                                           const __half* __restrict__ Gsrc,
                                           int chunk, int tid) {
#pragma unroll 2
    for (int i = tid; i < 128 * 12; i += 256) {
        int row = i / 12, q = i % 12;
        cp16(dstBase + row * CH_STRIDE + q * 16,
             Gsrc + (size_t)row * TK + chunk * 96 + q * 8);
    }
}

__global__ void __launch_bounds__(256, 1) big_syrk_mma(
    const __half* __restrict__ Gb, float* __restrict__ C)
{
    extern __shared__ char smem[];
    const uint32_t smA0 = smem_u32(smem);
    const uint32_t smA1 = smA0 + CH_BYTES;
    const uint32_t smB0 = smA1 + CH_BYTES;
    const uint32_t smB1 = smB0 + CH_BYTES;

    const int tid = threadIdx.x;
    const int wid = tid >> 5;
    const int lid = tid & 31;

    int idx = blockIdx.x;
    int bi = 0;
    while (bi < 63 && (64 * (bi + 1) - ((bi + 1) * bi) / 2) <= idx) bi++;
    int bj = bi + (idx - (64 * bi - (bi * (bi - 1)) / 2));

    const __half* GbA = Gb + (size_t)(bi * 128) * TK;
    const __half* GbB = Gb + (size_t)(bj * 128) * TK;

    // prologue: chunk0 (A0,B0) -> group1; chunk1 (A1,B1) -> group2
    load_chunk(smA0, GbA, 0, tid);
    load_chunk(smB0, GbB, 0, tid);
    cp_commit();
    load_chunk(smA1, GbA, 1, tid);
    load_chunk(smB1, GbB, 1, tid);
    cp_commit();

    const int wm = wid >> 2;
    const int wn = wid & 3;
    const int m_base = wm * 64;
    const int n0 = wn * 32;

    const int aRow = m_base + (lid & 15);
    const int aColH = (lid >> 4) * 8;
    const int bRow = n0 + ((lid >> 4) * 8) + (lid & 7);
    const int bColH = ((lid >> 3) & 1) * 8;

    float acc[4][4][4];
#pragma unroll
    for (int mf = 0; mf < 4; mf++)
#pragma unroll
        for (int nf = 0; nf < 4; nf++)
#pragma unroll
            for (int q = 0; q < 4; q++) acc[mf][nf][q] = 0.f;

#pragma unroll
    for (int c = 0; c < 2; c++) {
        if (c == 0) cp_wait<1>(); else cp_wait<0>();
        __syncthreads();
        const uint32_t smAc = c ? smA1 : smA0;
        const uint32_t smBc = c ? smB1 : smB0;

#pragma unroll
        for (int s = 0; s < 6; s++) {
            const int kk = s * 16;                // same k-range for A and B
            uint32_t a[4][4];
#pragma unroll
            for (int mf = 0; mf < 4; mf++)
                ldm_x4(a[mf], smAc + (uint32_t)((aRow + mf * 16) * CH_STRIDE
                                                + (kk + aColH) * 2));
            uint32_t b[4][2];
#pragma unroll
            for (int q = 0; q < 2; q++) {
                uint32_t r[4];
                ldm_x4(r, smBc + (uint32_t)((bRow + q * 16) * CH_STRIDE
                                            + (kk + bColH) * 2));
                b[2 * q + 0][0] = r[0]; b[2 * q + 0][1] = r[1];
                b[2 * q + 1][0] = r[2]; b[2 * q + 1][1] = r[3];
            }
#pragma unroll
            for (int mf = 0; mf < 4; mf++)
#pragma unroll
                for (int nf = 0; nf < 4; nf++)
                    mma16816(acc[mf][nf], a[mf], b[nf]);
        }
    }

    // ---- epilogue ----
    const int r0g = bi * 128, c0g = bj * 128;
    const int lrow = lid >> 2;
    const int lcol = (lid & 3) * 2;

#pragma unroll
    for (int mf = 0; mf < 4; mf++) {
#pragma unroll
        for (int nf = 0; nf < 4; nf++) {
            int row = m_base + mf * 16 + lrow;
            int col = n0 + nf * 8 + lcol;
            float2 v0 = make_float2(0.5f * acc[mf][nf][0], 0.5f * acc[mf][nf][1]);
            float2 v1 = make_float2(0.5f * acc[mf][nf][2], 0.5f * acc[mf][nf][3]);
            *(float2*)(C + (size_t)(r0g + row) * NROWS + c0g + col)     = v0;
            *(float2*)(C + (size_t)(r0g + row + 8) * NROWS + c0g + col) = v1;
        }
    }

    if (bi != bj) {
        __syncthreads();                       // smem tiles no longer needed
        float* smT = (float*)smem;             // [128 cols][132] transpose buf
#pragma unroll
        for (int mf = 0; mf < 4; mf++) {
#pragma unroll
            for (int nf = 0; nf < 4; nf++) {
                int row = m_base + mf * 16 + lrow;
                int col = n0 + nf * 8 + lcol;
                smT[(col + 0) * 132 + row]     = 0.5f * acc[mf][nf][0];
                smT[(col + 1) * 132 + row]     = 0.5f * acc[mf][nf][1];
                smT[(col + 0) * 132 + row + 8] = 0.5f * acc[mf][nf][2];
                smT[(col + 1) * 132 + row + 8] = 0.5f * acc[mf][nf][3];
            }
        }
        __syncthreads();
        for (int i = tid; i < 128 * 32; i += 256) {
            int c = i >> 5, q = i & 31;
            float4 v = *(float4*)&smT[c * 132 + q * 4];
            *(float4*)(C + (size_t)(c0g + c) * NROWS + r0g + q * 4) = v;
        }
    }
}

// ---------------------------------------------------------------------------
// Launch
// Inputs: 0:x 1:adj 2:src 3:dst 4:fc_w 5:fc_b 6:w1 7:w1_b 8:w2 9:w2_b
//         10:epsilon 11:gamma 12:beta
// ---------------------------------------------------------------------------
extern "C" void kernel_launch(void* const* d_in, const int* in_sizes, int n_in,
                              void* d_out, int out_size)
{
    const float* x     = (const float*)d_in[0];
    const int*   src   = (const int*)d_in[2];
    const int*   dst   = (const int*)d_in[3];
    const float* fc_w  = (const float*)d_in[4];
    const float* fc_b  = (const float*)d_in[5];
    const float* w1    = (const float*)d_in[6];
    const float* w1_b  = (const float*)d_in[7];
    const float* w2    = (const float*)d_in[8];
    const float* w2_b  = (const float*)d_in[9];
    const float* epsv  = (const float*)d_in[10];
    const float* gamma = (const float*)d_in[11];
    const float* beta  = (const float*)d_in[12];
    const int E = in_sizes[2];

    float* out_ret = (float*)d_out;
    float* out_bn  = (float*)d_out + (size_t)RET_ELEMS;

    float *y1, *z1, *h1, *y2, *z2, *h, *stats;
    __half* Gb;
    cudaGetSymbolAddress((void**)&y1, g_y1);
    cudaGetSymbolAddress((void**)&z1, g_z1);
    cudaGetSymbolAddress((void**)&h1, g_h1);
    cudaGetSymbolAddress((void**)&y2, g_y2);
    cudaGetSymbolAddress((void**)&z2, g_z2);
    cudaGetSymbolAddress((void**)&h,  g_h);
    cudaGetSymbolAddress((void**)&Gb, g_Gb);
    cudaGetSymbolAddress((void**)&stats, g_stats);

    cudaFuncSetAttribute(big_syrk_mma, cudaFuncAttributeMaxDynamicSharedMemorySize,
                         SYRK_SMEM);

    // CSR build front half
    zero_small<<<(NROWS + 255) / 256, 256>>>();            // 0
    hist_kernel<<<256, 256>>>(dst, E);                     // 1
    scan_kernel<<<1, 1024>>>();                            // 2

    // y1 = x @ w1 ; h1 = x @ fc_w + fc_b
    small_gemm<<<dim3(NROWS / 64, HID / 64), 256>>>(x, nullptr, w1, nullptr,
                                                    y1, NROWS, HID, 0);   // 3
    small_gemm<<<dim3(NROWS / 64, OUTC / 64), 256>>>(x, nullptr, fc_w, fc_b,
                                                     h1, NROWS, OUTC, 0); // 4

    // CSR scatter (only needs scan), then gathers
    scatter_kernel<<<256, 256>>>(src, dst, E);             // 5

    // z1 = segsum(y1)
    gather_kernel<32><<<NROWS * 32 / 256, 256>>>(y1, z1);  // 6

    // y2 = relu(z1 + w1_b) @ w2
    small_gemm<<<dim3(NROWS / 64, OUTC / 64), 256>>>(z1, w1_b, w2, nullptr,
                                                     y2, NROWS, OUTC, 1); // 7
    // z2 = segsum(y2)
    gather_kernel<16><<<NROWS * 16 / 256, 256>>>(y2, z2);  // 8

    build_h<<<NROWS / 8, dim3(64, 8)>>>(h1, z2, w2_b, x, epsv, h, Gb, stats); // 9
    bn_out<<<(NROWS * OUTC + 255) / 256, 256>>>(h, stats, gamma, beta, out_bn); // 10

    big_syrk_mma<<<(64 * 65) / 2, 256, SYRK_SMEM>>>(Gb, out_ret); // 11
}

// round 17
// speedup vs baseline: 1.3895x; 1.0531x over previous
#include <cuda_runtime.h>
#include <cuda_bf16.h>
#include <cuda_fp16.h>
#include <cstdint>
#include <math.h>

#define NROWS 8192
#define HID   128
#define OUTC  64
#define GDIM  192          // [h(64) | x(128)]
#define TK    192          // fp16 G (hi only; lo-half contributes ~2^-24 -> dropped)
#define EMAX  262144
#define RET_ELEMS (NROWS * NROWS)

// ---------------------------------------------------------------------------
// Scratch (device globals)
// ---------------------------------------------------------------------------
__device__ float g_y1[NROWS * HID];
__device__ float g_z1[NROWS * HID];
__device__ float g_h1[NROWS * OUTC];
__device__ float g_y2[NROWS * OUTC];
__device__ float g_z2[NROWS * OUTC];
__device__ float g_h [NROWS * OUTC];          // fp32 h for BN
__device__ __half g_Gb[NROWS * TK];           // fp16 G = [h | x]
__device__ float g_stats[2 * OUTC];
// CSR scratch
__device__ int g_deg[NROWS];
__device__ int g_off[NROWS + 1];
__device__ int g_cur[NROWS];
__device__ int g_csr[EMAX];

// ---------------------------------------------------------------------------
// helpers
// ---------------------------------------------------------------------------
__device__ __forceinline__ uint32_t smem_u32(const void* p) {
    uint32_t a;
    asm("{ .reg .u64 t; cvta.to.shared.u64 t, %1; cvt.u32.u64 %0, t; }" : "=r"(a) : "l"(p));
    return a;
}
__device__ __forceinline__ void ldm_x4(uint32_t* r, uint32_t addr) {
    asm volatile("ldmatrix.sync.aligned.m8n8.x4.shared.b16 {%0,%1,%2,%3}, [%4];"
                 : "=r"(r[0]), "=r"(r[1]), "=r"(r[2]), "=r"(r[3]) : "r"(addr));
}
__device__ __forceinline__ void mma16816(float* d, const uint32_t* a, const uint32_t* b) {
    asm volatile("mma.sync.aligned.m16n8k16.row.col.f32.f16.f16.f32 "
                 "{%0,%1,%2,%3}, {%4,%5,%6,%7}, {%8,%9}, {%0,%1,%2,%3};"
                 : "+f"(d[0]), "+f"(d[1]), "+f"(d[2]), "+f"(d[3])
                 : "r"(a[0]), "r"(a[1]), "r"(a[2]), "r"(a[3]), "r"(b[0]), "r"(b[1]));
}
__device__ __forceinline__ void cp16(uint32_t smem_dst, const void* gsrc) {
    asm volatile("cp.async.cg.shared.global [%0], [%1], 16;"
                 :: "r"(smem_dst), "l"(gsrc) : "memory");
}
__device__ __forceinline__ void cp_commit() {
    asm volatile("cp.async.commit_group;" ::: "memory");
}
template <int N>
__device__ __forceinline__ void cp_wait() {
    asm volatile("cp.async.wait_group %0;" :: "n"(N) : "memory");
}

// ---------------------------------------------------------------------------
// CSR build: zero -> histogram -> scan -> scatter (int4 edge loads)
// ---------------------------------------------------------------------------
__global__ void zero_small() {
    int i = blockIdx.x * blockDim.x + threadIdx.x;
    if (i < NROWS) g_deg[i] = 0;
    if (i < 2 * OUTC) g_stats[i] = 0.f;
}

__global__ void hist_kernel(const int* __restrict__ dst, int E) {
    int i = blockIdx.x * blockDim.x + threadIdx.x;
    int stride = gridDim.x * blockDim.x;
    int n4 = E >> 2;
    const int4* d4 = (const int4*)dst;
    for (int e = i; e < n4; e += stride) {
        int4 d = d4[e];
        atomicAdd(&g_deg[d.x], 1);
        atomicAdd(&g_deg[d.y], 1);
        atomicAdd(&g_deg[d.z], 1);
        atomicAdd(&g_deg[d.w], 1);
    }
}

__global__ void __launch_bounds__(1024) scan_kernel() {
    __shared__ int ssum[1024];
    int t = threadIdx.x;
    int v[8];
    int tot = 0;
#pragma unroll
    for (int j = 0; j < 8; j++) { v[j] = g_deg[t * 8 + j]; tot += v[j]; }
    ssum[t] = tot;
    __syncthreads();
    for (int d = 1; d < 1024; d <<= 1) {
        int x = (t >= d) ? ssum[t - d] : 0;
        __syncthreads();
        ssum[t] += x;
        __syncthreads();
    }
    int run = ssum[t] - tot;   // exclusive prefix
#pragma unroll
    for (int j = 0; j < 8; j++) {
        g_off[t * 8 + j] = run;
        g_cur[t * 8 + j] = run;
        run += v[j];
    }
    if (t == 1023) g_off[NROWS] = run;
}

__global__ void scatter_kernel(const int* __restrict__ src,
                               const int* __restrict__ dst, int E) {
    int i = blockIdx.x * blockDim.x + threadIdx.x;
    int stride = gridDim.x * blockDim.x;
    int n4 = E >> 2;
    const int4* s4 = (const int4*)src;
    const int4* d4 = (const int4*)dst;
    for (int e = i; e < n4; e += stride) {
        int4 s = s4[e];
        int4 d = d4[e];
        int p0 = atomicAdd(&g_cur[d.x], 1); g_csr[p0] = s.x;
        int p1 = atomicAdd(&g_cur[d.y], 1); g_csr[p1] = s.y;
        int p2 = atomicAdd(&g_cur[d.z], 1); g_csr[p2] = s.z;
        int p3 = atomicAdd(&g_cur[d.w], 1); g_csr[p3] = s.w;
    }
}

// ---------------------------------------------------------------------------
// CSR gather segment-sum
// ---------------------------------------------------------------------------
template <int TPD>
__global__ void __launch_bounds__(256) gather_kernel(
    const float* __restrict__ feat, float* __restrict__ out)
{
    const int F = TPD * 4;
    int g = (blockIdx.x * blockDim.x + threadIdx.x) / TPD;
    int lane = threadIdx.x % TPD;
    if (g >= NROWS) return;
    int b = g_off[g];
    int e = g_off[g + 1];
    float4 acc = make_float4(0.f, 0.f, 0.f, 0.f);
    float4 acc2 = make_float4(0.f, 0.f, 0.f, 0.f);
    int i = b;
    for (; i + 1 < e; i += 2) {
        int s0 = g_csr[i];
        int s1 = g_csr[i + 1];
        float4 v0 = *(const float4*)(feat + (size_t)s0 * F + lane * 4);
        float4 v1 = *(const float4*)(feat + (size_t)s1 * F + lane * 4);
        acc.x += v0.x; acc.y += v0.y; acc.z += v0.z; acc.w += v0.w;
        acc2.x += v1.x; acc2.y += v1.y; acc2.z += v1.z; acc2.w += v1.w;
    }
    if (i < e) {
        int s0 = g_csr[i];
        float4 v0 = *(const float4*)(feat + (size_t)s0 * F + lane * 4);
        acc.x += v0.x; acc.y += v0.y; acc.z += v0.z; acc.w += v0.w;
    }
    acc.x += acc2.x; acc.y += acc2.y; acc.z += acc2.z; acc.w += acc2.w;
    *(float4*)(out + (size_t)g * F + lane * 4) = acc;
}

// ---------------------------------------------------------------------------
// Fused x-GEMM: grid (128, 3).
//   blockIdx.y < 2 : y1[:, y*64 .. y*64+63] = x @ w1 columns
//   blockIdx.y == 2: h1 = x @ fc_w + fc_b
// Same inner tile algorithm as the known-good small_gemm.
// ---------------------------------------------------------------------------
__global__ void __launch_bounds__(256) xw_gemm(
    const float* __restrict__ x, const float* __restrict__ w1,
    const float* __restrict__ fc_w, const float* __restrict__ fc_b,
    float* __restrict__ y1, float* __restrict__ h1)
{
    __shared__ float As[16][64];
    __shared__ float Bs[16][64];
    const int row0 = blockIdx.x * 64;
    const bool is_fc = (blockIdx.y == 2);
    const int col0 = is_fc ? 0 : blockIdx.y * 64;
    const int Nc = is_fc ? OUTC : HID;
    const float* B = is_fc ? fc_w : w1;
    float* C = is_fc ? h1 : y1;
    const int tid = threadIdx.x;
    const int tx = tid & 15, ty = tid >> 4;

    float acc[4][4];
#pragma unroll
    for (int i = 0; i < 4; i++)
#pragma unroll
        for (int j = 0; j < 4; j++) acc[i][j] = 0.f;

    for (int k0 = 0; k0 < HID; k0 += 16) {
        {
            int r = tid >> 2;
            int c4 = (tid & 3) * 4;
            float4 v = *(const float4*)(x + (size_t)(row0 + r) * HID + k0 + c4);
            As[c4 + 0][r] = v.x; As[c4 + 1][r] = v.y;
            As[c4 + 2][r] = v.z; As[c4 + 3][r] = v.w;
        }
        {
            int kr = tid >> 4;
            int c = (tid & 15) * 4;
            float4 v = *(const float4*)(B + (size_t)(k0 + kr) * Nc + col0 + c);
            *(float4*)&Bs[kr][c] = v;
        }
        __syncthreads();
#pragma unroll
        for (int kk = 0; kk < 16; kk++) {
            float av[4], bv[4];
#pragma unroll
            for (int i = 0; i < 4; i++) av[i] = As[kk][ty * 4 + i];
#pragma unroll
            for (int j = 0; j < 4; j++) bv[j] = Bs[kk][tx * 4 + j];
#pragma unroll
            for (int i = 0; i < 4; i++)
#pragma unroll
                for (int j = 0; j < 4; j++) acc[i][j] += av[i] * bv[j];
        }
        __syncthreads();
    }
#pragma unroll
    for (int i = 0; i < 4; i++)
#pragma unroll
        for (int j = 0; j < 4; j++) {
            int c = col0 + tx * 4 + j;
            float cb = is_fc ? fc_b[c] : 0.f;
            C[(size_t)(row0 + ty * 4 + i) * Nc + c] = acc[i][j] + cb;
        }
}

// ---------------------------------------------------------------------------
// Small GEMM (for y2 = relu(z1 + w1_b) @ w2)
// ---------------------------------------------------------------------------
__global__ void __launch_bounds__(256) small_gemm(
    const float* __restrict__ A, const float* __restrict__ abias,
    const float* __restrict__ B, const float* __restrict__ cbias,
    float* __restrict__ C, int M, int Nc, int relu)
{
    __shared__ float As[16][64];
    __shared__ float Bs[16][64];
    const int row0 = blockIdx.x * 64;
    const int col0 = blockIdx.y * 64;
    const int tid = threadIdx.x;
    const int tx = tid & 15, ty = tid >> 4;

    float acc[4][4];
#pragma unroll
    for (int i = 0; i < 4; i++)
#pragma unroll
        for (int j = 0; j < 4; j++) acc[i][j] = 0.f;

    for (int k0 = 0; k0 < HID; k0 += 16) {
        {
            int r = tid >> 2;
            int c4 = (tid & 3) * 4;
            float4 v = *(const float4*)(A + (size_t)(row0 + r) * HID + k0 + c4);
            if (relu) {
                v.x = fmaxf(v.x + abias[k0 + c4 + 0], 0.f);
                v.y = fmaxf(v.y + abias[k0 + c4 + 1], 0.f);
                v.z = fmaxf(v.z + abias[k0 + c4 + 2], 0.f);
                v.w = fmaxf(v.w + abias[k0 + c4 + 3], 0.f);
            }
            As[c4 + 0][r] = v.x; As[c4 + 1][r] = v.y;
            As[c4 + 2][r] = v.z; As[c4 + 3][r] = v.w;
        }
        {
            int kr = tid >> 4;
            int c = (tid & 15) * 4;
            float4 v = *(const float4*)(B + (size_t)(k0 + kr) * Nc + col0 + c);
            *(float4*)&Bs[kr][c] = v;
        }
        __syncthreads();
#pragma unroll
        for (int kk = 0; kk < 16; kk++) {
            float av[4], bv[4];
#pragma unroll
            for (int i = 0; i < 4; i++) av[i] = As[kk][ty * 4 + i];
#pragma unroll
            for (int j = 0; j < 4; j++) bv[j] = Bs[kk][tx * 4 + j];
#pragma unroll
            for (int i = 0; i < 4; i++)
#pragma unroll
                for (int j = 0; j < 4; j++) acc[i][j] += av[i] * bv[j];
        }
        __syncthreads();
    }
#pragma unroll
    for (int i = 0; i < 4; i++)
#pragma unroll
        for (int j = 0; j < 4; j++) {
            int c = col0 + tx * 4 + j;
            float cb = cbias ? cbias[c] : 0.f;
            C[(size_t)(row0 + ty * 4 + i) * Nc + c] = acc[i][j] + cb;
        }
}

// ---------------------------------------------------------------------------
// Build h, fp16 G=[h|x] into g_Gb, BN stats.
// ---------------------------------------------------------------------------
__global__ void build_h(const float* __restrict__ h1, const float* __restrict__ z2,
                        const float* __restrict__ w2b, const float* __restrict__ x,
                        const float* __restrict__ epsv,
                        float* __restrict__ h_out, __half* __restrict__ Gb,
                        float* __restrict__ stats)
{
    __shared__ float ssum[OUTC];
    __shared__ float ssq[OUTC];
    int c = threadIdx.x;
    int ty = threadIdx.y;
    if (ty == 0) { ssum[c] = 0.f; ssq[c] = 0.f; }
    __syncthreads();

    size_t r = blockIdx.x * 8 + ty;
    float e  = epsv[r];
    float hv = (1.f - e) * h1[r * OUTC + c] + e * (z2[r * OUTC + c] + w2b[c]);
    h_out[r * OUTC + c] = hv;
    Gb[r * TK + c]             = __float2half(hv);
    Gb[r * TK + OUTC + c]      = __float2half(x[r * HID + c]);
    Gb[r * TK + OUTC + 64 + c] = __float2half(x[r * HID + 64 + c]);
    atomicAdd(&ssum[c], hv);
    atomicAdd(&ssq[c], hv * hv);
    __syncthreads();
    if (ty == 0) {
        atomicAdd(&stats[c], ssum[c]);
        atomicAdd(&stats[OUTC + c], ssq[c]);
    }
}

__global__ void bn_out(const float* __restrict__ h, const float* __restrict__ stats,
                       const float* __restrict__ gamma, const float* __restrict__ beta,
                       float* __restrict__ out)
{
    int i = blockIdx.x * blockDim.x + threadIdx.x;
    if (i >= NROWS * OUTC) return;
    int c = i & 63;
    float inv = 1.f / (float)NROWS;
    float mean = stats[c] * inv;
    float var  = stats[OUTC + c] * inv - mean * mean;
    out[i] = (h[i] - mean) * rsqrtf(var + 1e-5f) * gamma[c] + beta[c];
}

// ---------------------------------------------------------------------------
// HMMA SYRK over plain fp16 G (K=192, 12 k16-steps).
// launch_bounds(256,2): 2 CTAs/SM (2x104KB smem = 208KB <= 228KB carveout)
// so one CTA's MMA covers the other's prologue loads and epilogue stores.
// ---------------------------------------------------------------------------
#define CH_STRIDE 208                           // 96 fp16 padded to 104 (208B)
#define CH_BYTES  (128 * CH_STRIDE)             // 26624
#define SYRK_SMEM (4 * CH_BYTES)                // 106496 (A0,A1,B0,B1)

__device__ __forceinline__ void load_chunk(uint32_t dstBase,
                                           const __half* __restrict__ Gsrc,
                                           int chunk, int tid) {
#pragma unroll 2
    for (int i = tid; i < 128 * 12; i += 256) {
        int row = i / 12, q = i % 12;
        cp16(dstBase + row * CH_STRIDE + q * 16,
             Gsrc + (size_t)row * TK + chunk * 96 + q * 8);
    }
}

__global__ void __launch_bounds__(256, 2) big_syrk_mma(
    const __half* __restrict__ Gb, float* __restrict__ C)
{
    extern __shared__ char smem[];
    const uint32_t smA0 = smem_u32(smem);
    const uint32_t smA1 = smA0 + CH_BYTES;
    const uint32_t smB0 = smA1 + CH_BYTES;
    const uint32_t smB1 = smB0 + CH_BYTES;

    const int tid = threadIdx.x;
    const int wid = tid >> 5;
    const int lid = tid & 31;

    int idx = blockIdx.x;
    int bi = 0;
    while (bi < 63 && (64 * (bi + 1) - ((bi + 1) * bi) / 2) <= idx) bi++;
    int bj = bi + (idx - (64 * bi - (bi * (bi - 1)) / 2));

    const __half* GbA = Gb + (size_t)(bi * 128) * TK;
    const __half* GbB = Gb + (size_t)(bj * 128) * TK;

    // prologue: chunk0 (A0,B0) -> group1; chunk1 (A1,B1) -> group2
    load_chunk(smA0, GbA, 0, tid);
    load_chunk(smB0, GbB, 0, tid);
    cp_commit();
    load_chunk(smA1, GbA, 1, tid);
    load_chunk(smB1, GbB, 1, tid);
    cp_commit();

    const int wm = wid >> 2;
    const int wn = wid & 3;
    const int m_base = wm * 64;
    const int n0 = wn * 32;

    const int aRow = m_base + (lid & 15);
    const int aColH = (lid >> 4) * 8;
    const int bRow = n0 + ((lid >> 4) * 8) + (lid & 7);
    const int bColH = ((lid >> 3) & 1) * 8;

    float acc[4][4][4];
#pragma unroll
    for (int mf = 0; mf < 4; mf++)
#pragma unroll
        for (int nf = 0; nf < 4; nf++)
#pragma unroll
            for (int q = 0; q < 4; q++) acc[mf][nf][q] = 0.f;

#pragma unroll
    for (int c = 0; c < 2; c++) {
        if (c == 0) cp_wait<1>(); else cp_wait<0>();
        __syncthreads();
        const uint32_t smAc = c ? smA1 : smA0;
        const uint32_t smBc = c ? smB1 : smB0;

#pragma unroll
        for (int s = 0; s < 6; s++) {
            const int kk = s * 16;                // same k-range for A and B
            uint32_t a[4][4];
#pragma unroll
            for (int mf = 0; mf < 4; mf++)
                ldm_x4(a[mf], smAc + (uint32_t)((aRow + mf * 16) * CH_STRIDE
                                                + (kk + aColH) * 2));
            uint32_t b[4][2];
#pragma unroll
            for (int q = 0; q < 2; q++) {
                uint32_t r[4];
                ldm_x4(r, smBc + (uint32_t)((bRow + q * 16) * CH_STRIDE
                                            + (kk + bColH) * 2));
                b[2 * q + 0][0] = r[0]; b[2 * q + 0][1] = r[1];
                b[2 * q + 1][0] = r[2]; b[2 * q + 1][1] = r[3];
            }
#pragma unroll
            for (int mf = 0; mf < 4; mf++)
#pragma unroll
                for (int nf = 0; nf < 4; nf++)
                    mma16816(acc[mf][nf], a[mf], b[nf]);
        }
    }

    // ---- epilogue ----
    const int r0g = bi * 128, c0g = bj * 128;
    const int lrow = lid >> 2;
    const int lcol = (lid & 3) * 2;

#pragma unroll
    for (int mf = 0; mf < 4; mf++) {
#pragma unroll
        for (int nf = 0; nf < 4; nf++) {
            int row = m_base + mf * 16 + lrow;
            int col = n0 + nf * 8 + lcol;
            float2 v0 = make_float2(0.5f * acc[mf][nf][0], 0.5f * acc[mf][nf][1]);
            float2 v1 = make_float2(0.5f * acc[mf][nf][2], 0.5f * acc[mf][nf][3]);
            *(float2*)(C + (size_t)(r0g + row) * NROWS + c0g + col)     = v0;
            *(float2*)(C + (size_t)(r0g + row + 8) * NROWS + c0g + col) = v1;
        }
    }

    if (bi != bj) {
        __syncthreads();                       // smem tiles no longer needed
        float* smT = (float*)smem;             // [128 cols][132] transpose buf
#pragma unroll
        for (int mf = 0; mf < 4; mf++) {
#pragma unroll
            for (int nf = 0; nf < 4; nf++) {
                int row = m_base + mf * 16 + lrow;
                int col = n0 + nf * 8 + lcol;
                smT[(col + 0) * 132 + row]     = 0.5f * acc[mf][nf][0];
                smT[(col + 1) * 132 + row]     = 0.5f * acc[mf][nf][1];
                smT[(col + 0) * 132 + row + 8] = 0.5f * acc[mf][nf][2];
                smT[(col + 1) * 132 + row + 8] = 0.5f * acc[mf][nf][3];
            }
        }
        __syncthreads();
        for (int i = tid; i < 128 * 32; i += 256) {
            int c = i >> 5, q = i & 31;
            float4 v = *(float4*)&smT[c * 132 + q * 4];
            *(float4*)(C + (size_t)(c0g + c) * NROWS + r0g + q * 4) = v;
        }
    }
}

// ---------------------------------------------------------------------------
// Launch
// Inputs: 0:x 1:adj 2:src 3:dst 4:fc_w 5:fc_b 6:w1 7:w1_b 8:w2 9:w2_b
//         10:epsilon 11:gamma 12:beta
// ---------------------------------------------------------------------------
extern "C" void kernel_launch(void* const* d_in, const int* in_sizes, int n_in,
                              void* d_out, int out_size)
{
    const float* x     = (const float*)d_in[0];
    const int*   src   = (const int*)d_in[2];
    const int*   dst   = (const int*)d_in[3];
    const float* fc_w  = (const float*)d_in[4];
    const float* fc_b  = (const float*)d_in[5];
    const float* w1    = (const float*)d_in[6];
    const float* w1_b  = (const float*)d_in[7];
    const float* w2    = (const float*)d_in[8];
    const float* w2_b  = (const float*)d_in[9];
    const float* epsv  = (const float*)d_in[10];
    const float* gamma = (const float*)d_in[11];
    const float* beta  = (const float*)d_in[12];
    const int E = in_sizes[2];

    float* out_ret = (float*)d_out;
    float* out_bn  = (float*)d_out + (size_t)RET_ELEMS;

    float *y1, *z1, *h1, *y2, *z2, *h, *stats;
    __half* Gb;
    cudaGetSymbolAddress((void**)&y1, g_y1);
    cudaGetSymbolAddress((void**)&z1, g_z1);
    cudaGetSymbolAddress((void**)&h1, g_h1);
    cudaGetSymbolAddress((void**)&y2, g_y2);
    cudaGetSymbolAddress((void**)&z2, g_z2);
    cudaGetSymbolAddress((void**)&h,  g_h);
    cudaGetSymbolAddress((void**)&Gb, g_Gb);
    cudaGetSymbolAddress((void**)&stats, g_stats);

    cudaFuncSetAttribute(big_syrk_mma, cudaFuncAttributeMaxDynamicSharedMemorySize,
                         SYRK_SMEM);

    // CSR build front half
    zero_small<<<(NROWS + 255) / 256, 256>>>();            // 0
    hist_kernel<<<256, 256>>>(dst, E);                     // 1
    scan_kernel<<<1, 1024>>>();                            // 2

    // y1 = x @ w1 AND h1 = x @ fc_w + fc_b, fused (slot 3 -> profiled)
    xw_gemm<<<dim3(NROWS / 64, 3), 256>>>(x, w1, fc_w, fc_b, y1, h1); // 3

    // CSR scatter (only needs scan), then gathers
    scatter_kernel<<<256, 256>>>(src, dst, E);             // 4

    // z1 = segsum(y1)
    gather_kernel<32><<<NROWS * 32 / 256, 256>>>(y1, z1);  // 5

    // y2 = relu(z1 + w1_b) @ w2
    small_gemm<<<dim3(NROWS / 64, OUTC / 64), 256>>>(z1, w1_b, w2, nullptr,
                                                     y2, NROWS, OUTC, 1); // 6
    // z2 = segsum(y2)
    gather_kernel<16><<<NROWS * 16 / 256, 256>>>(y2, z2);  // 7

    build_h<<<NROWS / 8, dim3(64, 8)>>>(h1, z2, w2_b, x, epsv, h, Gb, stats); // 8
    bn_out<<<(NROWS * OUTC + 255) / 256, 256>>>(h, stats, gamma, beta, out_bn); // 9

    big_syrk_mma<<<(64 * 65) / 2, 256, SYRK_SMEM>>>(Gb, out_ret); // 10
}